// round 8
// baseline (speedup 1.0000x reference)
#include <cuda_runtime.h>
#include <cstdint>
#include <mma.h>

using namespace nvcuda;

// ---------------------------------------------------------------------------
// MoE HyperModel, round 7: wmma tf32, k_h fused into eo A-loader,
// K-tile 64, 2-stage cp.async pipeline, one sync per K-tile.
// (tcgen05 unavailable: harness PTX target is sm_103 without 'a'.)
// ---------------------------------------------------------------------------

namespace {
constexpr int kEMB = 1024;
constexpr int kCTX = 32;
constexpr int kNE  = 16;
constexpr int kH1  = 2048;
constexpr int kH2  = 512;
constexpr int kB   = 8;
constexpr int kM   = kCTX * kB;     // 256
constexpr int kFO  = 16384;
constexpr int kW1R = kEMB + kCTX;   // 1056

constexpr int kLDA = 68;    // smem A stride (floats): 128 rows x 64 k (+pad)
constexpr int kLDB = 260;   // smem B stride (floats): 64 rows x 256 n (+pad)
constexpr int kAstF = 128 * kLDA;        // 8704 floats
constexpr int kBstF = 64 * kLDB;         // 16640 floats
constexpr int kStF  = kAstF + kBstF;     // 25344 floats
constexpr int kSmemGemm = 2 * kStF * 4;  // 202752 bytes
}

// Scratch (static device arrays -- allocation-free).
__device__ float g_g1[kB * kH1];
__device__ float g_w[kB * kNE];
__device__ float g_base[kNE * kB * kH1];
__device__ float g_eo2[(size_t)2 * kNE * kM * kH2];   // split-K partials
__device__ float g_z[kM * kH2];

// --------------------------- cp.async helpers ------------------------------
__device__ __forceinline__ void cp_async16(float* smem_dst, const float* gmem_src) {
    unsigned int s = (unsigned int)__cvta_generic_to_shared(smem_dst);
    asm volatile("cp.async.cg.shared.global [%0], [%1], 16;\n" :: "r"(s), "l"(gmem_src));
}
__device__ __forceinline__ void cp_commit() {
    asm volatile("cp.async.commit_group;\n");
}
template <int N>
__device__ __forceinline__ void cp_wait() {
    asm volatile("cp.async.wait_group %0;\n" :: "n"(N));
}

// --------------------------- B stage loader --------------------------------
// 64 k-rows x 256 n, cp.async; B pre-offset to n0.
__device__ __forceinline__ void load_B(float* Bs, const float* B, int ldb,
                                       int kt, int t)
{
#pragma unroll
    for (int i = 0; i < 16; i++) {
        const int id = t + i * 256;
        const int r = id >> 6, c4 = (id & 63) * 4;
        cp_async16(Bs + r * kLDB + c4, B + (size_t)(kt + r) * ldb + c4);
    }
}

// --------------------------- A stage loaders -------------------------------
// eo (fused h): a[i] = tf32( w[b] * relu(base[b][k] + W1c[c][k]) )
__device__ __forceinline__ void load_A_eo(float4* a,
                                          const float* base_e, const float* w1c_e,
                                          const float* ws, int m0, int kt, int t)
{
#pragma unroll
    for (int i = 0; i < 8; i++) {
        const int id = t + i * 256;
        const int mloc = id >> 4, kc = (id & 15) * 4;
        const int m = m0 + mloc;
        const int b = m & 7, c = m >> 3;
        const float4 bs = *reinterpret_cast<const float4*>(base_e + (size_t)b * kH1 + kt + kc);
        const float4 wc = *reinterpret_cast<const float4*>(w1c_e + (size_t)c * kH1 + kt + kc);
        const float w = ws[b];
        a[i].x = wmma::__float_to_tf32(w * fmaxf(bs.x + wc.x, 0.f));
        a[i].y = wmma::__float_to_tf32(w * fmaxf(bs.y + wc.y, 0.f));
        a[i].z = wmma::__float_to_tf32(w * fmaxf(bs.z + wc.z, 0.f));
        a[i].w = wmma::__float_to_tf32(w * fmaxf(bs.w + wc.w, 0.f));
    }
}
__device__ __forceinline__ void sts_A(float* As, const float4* a, int t)
{
#pragma unroll
    for (int i = 0; i < 8; i++) {
        const int id = t + i * 256;
        const int mloc = id >> 4, kc = (id & 15) * 4;
        *reinterpret_cast<float4*>(As + mloc * kLDA + kc) = a[i];
    }
}
// out: plain cp.async A from g_z
__device__ __forceinline__ void load_A_cp(float* As, const float* A, int lda,
                                          int kt, int t)
{
#pragma unroll
    for (int i = 0; i < 8; i++) {
        const int id = t + i * 256;
        const int m = id >> 4, kc = (id & 15) * 4;
        cp_async16(As + m * kLDA + kc, A + (size_t)m * lda + kt + kc);
    }
}

// --------------------------- compute: warp 64x64, k-tile 64 ----------------
__device__ __forceinline__ void tile_compute64(
    const float* stage, int wm, int wn,
    wmma::fragment<wmma::accumulator, 16, 16, 8, float> (&acc)[4][4])
{
    const float* As = stage;
    const float* Bs = stage + kAstF;
#pragma unroll
    for (int kk = 0; kk < 8; kk++) {
        wmma::fragment<wmma::matrix_b, 16, 16, 8, wmma::precision::tf32, wmma::row_major> bf[4];
#pragma unroll
        for (int j = 0; j < 4; j++) {
            wmma::load_matrix_sync(bf[j], Bs + (kk * 8) * kLDB + wn * 64 + j * 16, kLDB);
#pragma unroll
            for (int u = 0; u < bf[j].num_elements; u++)
                bf[j].x[u] = wmma::__float_to_tf32(bf[j].x[u]);
        }
#pragma unroll
        for (int i = 0; i < 4; i++) {
            wmma::fragment<wmma::matrix_a, 16, 16, 8, wmma::precision::tf32, wmma::row_major> af;
            wmma::load_matrix_sync(af, As + (wm * 64 + i * 16) * kLDA + kk * 8, kLDA);
#pragma unroll
            for (int j = 0; j < 4; j++)
                wmma::mma_sync(acc[i][j], af, bf[j], acc[i][j]);
        }
    }
}

// ---------------------------------------------------------------------------
// k_base: base[e,b,:] = s @ W1s[e] + b1[e]; e==16 -> gating g1 (relu).
// ---------------------------------------------------------------------------
__global__ __launch_bounds__(256) void k_base(
    const float* __restrict__ s,
    const float* __restrict__ W1, const float* __restrict__ b1,
    const float* __restrict__ Wg1, const float* __restrict__ bg1)
{
    __shared__ float ssm[kB * kEMB];
    __shared__ float red[128][kB];
    const int t = threadIdx.x;
    const int e = blockIdx.y;
    const int jl = t & 127;
    const int half = t >> 7;
    const int j = blockIdx.x * 128 + jl;

    for (int i = t; i < kB * kEMB; i += 256) ssm[i] = s[i];
    __syncthreads();

    const float* __restrict__ W = (e < kNE) ? (W1 + (size_t)e * kW1R * kH1) : Wg1;

    float acc[kB];
#pragma unroll
    for (int b = 0; b < kB; b++) acc[b] = 0.f;

    const int i0 = half * 512;
#pragma unroll 4
    for (int i = i0; i < i0 + 512; i++) {
        const float w = W[(size_t)i * kH1 + j];
#pragma unroll
        for (int b = 0; b < kB; b++) acc[b] += ssm[b * kEMB + i] * w;
    }

    if (half) {
#pragma unroll
        for (int b = 0; b < kB; b++) red[jl][b] = acc[b];
    }
    __syncthreads();
    if (!half) {
#pragma unroll
        for (int b = 0; b < kB; b++) acc[b] += red[jl][b];
        if (e < kNE) {
            const float bias = b1[e * kH1 + j];
#pragma unroll
            for (int b = 0; b < kB; b++)
                g_base[((size_t)e * kB + b) * kH1 + j] = acc[b] + bias;
        } else {
            const float bias = bg1[j];
#pragma unroll
            for (int b = 0; b < kB; b++)
                g_g1[b * kH1 + j] = fmaxf(acc[b] + bias, 0.f);
        }
    }
}

// ---------------------------------------------------------------------------
// k_gate
// ---------------------------------------------------------------------------
__global__ __launch_bounds__(1024) void k_gate(
    const float* __restrict__ Wg2, const float* __restrict__ bg2)
{
    __shared__ float red[1024];
    const int t = threadIdx.x;
    const int b = t >> 7;
    const int rem = t & 127;
    const int kc = rem >> 4;
    const int x = rem & 15;

    float acc = 0.f;
    const int j0 = kc * 256;
#pragma unroll 4
    for (int j = j0; j < j0 + 256; j++)
        acc += g_g1[b * kH1 + j] * Wg2[j * kNE + x];
    red[t] = acc;
    __syncthreads();

    if (t < 128) {
        const int bb = t >> 4;
        const int xx = t & 15;
        float a = bg2[xx];
#pragma unroll
        for (int k = 0; k < 8; k++) a += red[bb * 128 + k * 16 + xx];

        float mx = a;
#pragma unroll
        for (int o = 8; o >= 1; o >>= 1)
            mx = fmaxf(mx, __shfl_xor_sync(0xffffffffu, mx, o, 16));
        const float ev = expf(a - mx);
        float sm = ev;
#pragma unroll
        for (int o = 8; o >= 1; o >>= 1)
            sm += __shfl_xor_sync(0xffffffffu, sm, o, 16);

        g_w[bb * kNE + xx] = ev / sm;
    }
}

// ---------------------------------------------------------------------------
// k_gemm_eo: fused-h split-K per-expert GEMM.
// A built on the fly: tf32(w * relu(base + W1c)); B = W2 (cp.async).
// Grid: (2 ntiles, 2 mtiles, 32 = expert*2 + khalf). K per CTA = 1024.
// ---------------------------------------------------------------------------
__global__ __launch_bounds__(256) void k_gemm_eo(
    const float* __restrict__ W1, const float* __restrict__ W2)
{
    extern __shared__ float smem[];
    __shared__ float ws[kB];

    const int t = threadIdx.x;
    const int warp = t >> 5;
    const int wm = warp >> 2;   // 0..1
    const int wn = warp & 3;    // 0..3
    const int zz = blockIdx.z, e = zz >> 1, kh = zz & 1;
    const int m0 = blockIdx.y * 128;
    const int n0 = blockIdx.x * 256;

    if (t < kB) ws[t] = g_w[t * kNE + e];

    const float* base_e = g_base + (size_t)e * kB * kH1 + kh * 1024;
    const float* w1c_e  = W1 + ((size_t)e * kW1R + kEMB) * kH1 + kh * 1024;
    const float* B      = W2 + (size_t)e * kH1 * kH2 + (size_t)(kh * 1024) * kH2 + n0;

    wmma::fragment<wmma::accumulator, 16, 16, 8, float> acc[4][4];
#pragma unroll
    for (int i = 0; i < 4; i++)
#pragma unroll
        for (int j = 0; j < 4; j++) wmma::fill_fragment(acc[i][j], 0.f);

    __syncthreads();   // ws visible

    constexpr int NT = 1024 / 64;   // 16
    float4 a[8];
    load_A_eo(a, base_e, w1c_e, ws, m0, 0, t);
    load_B(smem + kAstF, B, kH2, 0, t);
    cp_commit();
    sts_A(smem, a, t);
    load_A_eo(a, base_e, w1c_e, ws, m0, 64, t);

    for (int it = 0; it < NT; it++) {
        cp_wait<0>();
        __syncthreads();
        float* nxt = smem + ((it + 1) & 1) * kStF;
        if (it + 1 < NT) {
            load_B(nxt + kAstF, B, kH2, (it + 1) * 64, t);
            cp_commit();
            sts_A(nxt, a, t);
        }
        if (it + 2 < NT)
            load_A_eo(a, base_e, w1c_e, ws, m0, (it + 2) * 64, t);
        tile_compute64(smem + (it & 1) * kStF, wm, wn, acc);
    }

    float* O = g_eo2 + (size_t)zz * kM * kH2 + (size_t)m0 * kH2 + n0;
#pragma unroll
    for (int i = 0; i < 4; i++)
#pragma unroll
        for (int j = 0; j < 4; j++)
            wmma::store_matrix_sync(O + (size_t)(wm * 64 + i * 16) * kH2 + wn * 64 + j * 16,
                                    acc[i][j], kH2, wmma::mem_row_major);
}

// ---------------------------------------------------------------------------
// k_z: z = tf32( sum over 32 partial slabs + sum_e w[b,e]*b2[e] ).
// ---------------------------------------------------------------------------
__global__ __launch_bounds__(256) void k_z(const float* __restrict__ b2)
{
    const int idx = blockIdx.x * 256 + threadIdx.x;
    const int n = idx & (kH2 - 1);
    const int m = idx >> 9;
    const int b = m & 7;

    float acc = 0.f;
#pragma unroll
    for (int p = 0; p < 2 * kNE; p++)
        acc += g_eo2[(size_t)p * (kM * kH2) + idx];
#pragma unroll
    for (int e = 0; e < kNE; e++)
        acc += g_w[b * kNE + e] * b2[e * kH2 + n];
    g_z[idx] = wmma::__float_to_tf32(acc);
}

// ---------------------------------------------------------------------------
// k_gemm_out: z(256x512) @ {WA,WB}(512x16384) + bias -> out.
// Grid: (64 ntiles, 2 mtiles, 2 mats). K = 512, 8 K-tiles of 64.
// ---------------------------------------------------------------------------
__global__ __launch_bounds__(256) void k_gemm_out(
    const float* __restrict__ WA, const float* __restrict__ bA,
    const float* __restrict__ WB, const float* __restrict__ bB,
    float* __restrict__ out)
{
    extern __shared__ float smem[];

    const int t = threadIdx.x;
    const int warp = t >> 5;
    const int wm = warp >> 2;
    const int wn = warp & 3;
    const int mat = blockIdx.z;
    const int m0 = blockIdx.y * 128;
    const int n0 = blockIdx.x * 256;

    const float* __restrict__ Bw   = mat ? WB : WA;
    const float* __restrict__ bias = mat ? bB : bA;

    const float* A = g_z + (size_t)m0 * kH2;
    const float* B = Bw + n0;

    wmma::fragment<wmma::accumulator, 16, 16, 8, float> acc[4][4];
#pragma unroll
    for (int i = 0; i < 4; i++)
#pragma unroll
        for (int j = 0; j < 4; j++) wmma::fill_fragment(acc[i][j], 0.f);

    constexpr int NT = kH2 / 64;   // 8
    load_A_cp(smem, A, kH2, 0, t);
    load_B(smem + kAstF, B, kFO, 0, t);
    cp_commit();

    for (int it = 0; it < NT; it++) {
        cp_wait<0>();
        __syncthreads();
        if (it + 1 < NT) {
            float* nxt = smem + ((it + 1) & 1) * kStF;
            load_A_cp(nxt, A, kH2, (it + 1) * 64, t);
            load_B(nxt + kAstF, B, kFO, (it + 1) * 64, t);
            cp_commit();
        }
        tile_compute64(smem + (it & 1) * kStF, wm, wn, acc);
    }

    // Epilogue: stage 128x256 (stride 260) in smem, add bias, float4 stores.
    __syncthreads();
#pragma unroll
    for (int i = 0; i < 4; i++)
#pragma unroll
        for (int j = 0; j < 4; j++)
            wmma::store_matrix_sync(smem + (wm * 64 + i * 16) * kLDB + wn * 64 + j * 16,
                                    acc[i][j], kLDB, wmma::mem_row_major);
    __syncthreads();

    float* O = out + (size_t)mat * kM * kFO + (size_t)m0 * kFO + n0;
#pragma unroll
    for (int i = 0; i < 32; i++) {
        const int id = t + i * 256;
        const int r = id >> 6, c4 = (id & 63) * 4;
        float4 v  = *reinterpret_cast<const float4*>(smem + r * kLDB + c4);
        const float4 bv = *reinterpret_cast<const float4*>(bias + n0 + c4);
        v.x += bv.x; v.y += bv.y; v.z += bv.z; v.w += bv.w;
        *reinterpret_cast<float4*>(O + (size_t)r * kFO + c4) = v;
    }
}

// ---------------------------------------------------------------------------
// kernel_launch
// ---------------------------------------------------------------------------
extern "C" void kernel_launch(void* const* d_in, const int* in_sizes, int n_in,
                              void* d_out, int out_size)
{
    const float* s   = (const float*)d_in[0];
    const float* Wg1 = (const float*)d_in[1];
    const float* bg1 = (const float*)d_in[2];
    const float* Wg2 = (const float*)d_in[3];
    const float* bg2 = (const float*)d_in[4];
    const float* W1  = (const float*)d_in[5];
    const float* b1  = (const float*)d_in[6];
    const float* W2  = (const float*)d_in[7];
    const float* b2  = (const float*)d_in[8];
    const float* WA  = (const float*)d_in[9];
    const float* bA  = (const float*)d_in[10];
    const float* WB  = (const float*)d_in[11];
    const float* bB  = (const float*)d_in[12];
    float* out = (float*)d_out;

    cudaFuncSetAttribute(k_gemm_eo,  cudaFuncAttributeMaxDynamicSharedMemorySize, kSmemGemm);
    cudaFuncSetAttribute(k_gemm_out, cudaFuncAttributeMaxDynamicSharedMemorySize, kSmemGemm);

    k_base<<<dim3(kH1 / 128, kNE + 1), 256>>>(s, W1, b1, Wg1, bg1);
    k_gate<<<1, 1024>>>(Wg2, bg2);
    k_gemm_eo<<<dim3(2, 2, 2 * kNE), 256, kSmemGemm>>>(W1, W2);
    k_z<<<(kM * kH2) / 256, 256>>>(b2);
    k_gemm_out<<<dim3(kFO / 256, kM / 128, 2), 256, kSmemGemm>>>(WA, bA, WB, bB, out);
}